// round 1
// baseline (speedup 1.0000x reference)
#include <cuda_runtime.h>
#include <math.h>

#define DIMV   1024
#define HEADS  16
#define DH     64
#define BATCH  4
#define SEQ    1024
#define BH     (BATCH*HEADS)
#define MROWS  (BATCH*SEQ)     // 4096

// ---------------- device scratch (no allocations allowed) ----------------
__device__ float g_Qr[BH*SEQ*DH];
__device__ float g_Qi[BH*SEQ*DH];
__device__ float g_Kr[BH*SEQ*DH];
__device__ float g_Ki[BH*SEQ*DH];
__device__ float g_Vr[BH*SEQ*DH];
__device__ float g_Vi[BH*SEQ*DH];
__device__ float g_Or[BATCH*SEQ*DIMV];
__device__ float g_Oi[BATCH*SEQ*DIMV];

// =================== complex GEMM:  C = A @ W^T + bias ===================
// A: [4096,1024] row-major (Ar,Ai), W: [1024,1024] row-major (so W^T => NT GEMM)
// mode 0/1/2 : A = x, C = Q/K/V written in head layout [bh][n][dh]
// mode 3     : A = g_O, C = outR/outI (flat [B,N,D]) = final output planes
__global__ void __launch_bounds__(256, 2) cgemm_kernel(
    const float* __restrict__ xr, const float* __restrict__ xi,
    const float* __restrict__ Wr, const float* __restrict__ Wi,
    const float* __restrict__ biasR, const float* __restrict__ biasI,
    float* __restrict__ outR, float* __restrict__ outI, int mode)
{
    __shared__ float Asr[16][128];
    __shared__ float Asi[16][128];
    __shared__ float Bsr[16][64];
    __shared__ float Bsi[16][64];

    const float* Ar = (mode == 3) ? g_Or : xr;
    const float* Ai = (mode == 3) ? g_Oi : xi;
    float* Cr;
    float* Ci;
    if      (mode == 0) { Cr = g_Qr; Ci = g_Qi; }
    else if (mode == 1) { Cr = g_Kr; Ci = g_Ki; }
    else if (mode == 2) { Cr = g_Vr; Ci = g_Vi; }
    else                { Cr = outR; Ci = outI; }

    const int tid = threadIdx.x;
    const int tx = tid & 15;        // n direction (16 * TN=4 = 64)
    const int ty = tid >> 4;        // m direction (16 * TM=8 = 128)
    const int rowBase = blockIdx.y * 128;
    const int colBase = blockIdx.x * 64;

    float cr[8][4];
    float cim[8][4];
#pragma unroll
    for (int i = 0; i < 8; i++)
#pragma unroll
        for (int j = 0; j < 4; j++) { cr[i][j] = 0.f; cim[i][j] = 0.f; }

    const int lrow = tid >> 2;           // 0..63
    const int lkq  = (tid & 3) << 2;     // 0,4,8,12

    for (int k0 = 0; k0 < 1024; k0 += 16) {
        // ---- stage A tile (128x16), transposed into smem ----
#pragma unroll
        for (int s = 0; s < 2; s++) {
            const int row = lrow + s * 64;
            const size_t off = (size_t)(rowBase + row) * 1024 + k0 + lkq;
            float4 a = *(const float4*)(Ar + off);
            Asr[lkq + 0][row] = a.x; Asr[lkq + 1][row] = a.y;
            Asr[lkq + 2][row] = a.z; Asr[lkq + 3][row] = a.w;
            float4 b = *(const float4*)(Ai + off);
            Asi[lkq + 0][row] = b.x; Asi[lkq + 1][row] = b.y;
            Asi[lkq + 2][row] = b.z; Asi[lkq + 3][row] = b.w;
        }
        // ---- stage W tile (64x16), transposed ----
        {
            const size_t off = (size_t)(colBase + lrow) * 1024 + k0 + lkq;
            float4 a = *(const float4*)(Wr + off);
            Bsr[lkq + 0][lrow] = a.x; Bsr[lkq + 1][lrow] = a.y;
            Bsr[lkq + 2][lrow] = a.z; Bsr[lkq + 3][lrow] = a.w;
            float4 b = *(const float4*)(Wi + off);
            Bsi[lkq + 0][lrow] = b.x; Bsi[lkq + 1][lrow] = b.y;
            Bsi[lkq + 2][lrow] = b.z; Bsi[lkq + 3][lrow] = b.w;
        }
        __syncthreads();

#pragma unroll
        for (int kk = 0; kk < 16; kk++) {
            float ar[8], ai[8], brv[4], biv[4];
            *(float4*)(&ar[0]) = *(const float4*)(&Asr[kk][ty * 8]);
            *(float4*)(&ar[4]) = *(const float4*)(&Asr[kk][ty * 8 + 4]);
            *(float4*)(&ai[0]) = *(const float4*)(&Asi[kk][ty * 8]);
            *(float4*)(&ai[4]) = *(const float4*)(&Asi[kk][ty * 8 + 4]);
            *(float4*)(&brv[0]) = *(const float4*)(&Bsr[kk][tx * 4]);
            *(float4*)(&biv[0]) = *(const float4*)(&Bsi[kk][tx * 4]);
#pragma unroll
            for (int i = 0; i < 8; i++) {
#pragma unroll
                for (int j = 0; j < 4; j++) {
                    cr[i][j]  = fmaf(ar[i],  brv[j], cr[i][j]);
                    cr[i][j]  = fmaf(-ai[i], biv[j], cr[i][j]);
                    cim[i][j] = fmaf(ar[i],  biv[j], cim[i][j]);
                    cim[i][j] = fmaf(ai[i],  brv[j], cim[i][j]);
                }
            }
        }
        __syncthreads();
    }

    // ---- epilogue ----
#pragma unroll
    for (int i = 0; i < 8; i++) {
        const int m = rowBase + ty * 8 + i;
#pragma unroll
        for (int j = 0; j < 4; j++) {
            const int c = colBase + tx * 4 + j;
            const float vr = cr[i][j]  + biasR[c];
            const float vi = cim[i][j] + biasI[c];
            size_t dst;
            if (mode != 3) {
                const int b = m >> 10, n = m & 1023;
                const int h = c >> 6,  d = c & 63;
                dst = ((size_t)(b * HEADS + h) * SEQ + n) * DH + d;
            } else {
                dst = (size_t)m * 1024 + c;
            }
            Cr[dst] = vr;
            Ci[dst] = vi;
        }
    }
}

// =================== attention kernel ===================
// grid: (SEQ/64, BH). One block = 64 queries of one (b,h).
// P = exp(sqrt(sim_r^2 + sim_i^2) / 8)  (logits >= 0 and bounded ~7, so no
// max-subtraction needed; identical math to reference softmax).
#define AP 68   // padded row stride (floats), multiple of 4, avoids bank conflicts

__global__ void __launch_bounds__(256) attn_kernel()
{
    extern __shared__ float sm[];
    float* Qr = sm;
    float* Qi = Qr + 64 * AP;
    float* Kr = Qi + 64 * AP;
    float* Ki = Kr + 64 * AP;
    float* Vr = Ki + 64 * AP;
    float* Vi = Vr + 64 * AP;
    float* P  = Vi + 64 * AP;
    float* rowsum = P + 64 * AP;

    const int tid = threadIdx.x;
    const int tq = tid >> 4;   // 0..15 -> query rows tq*4..tq*4+3
    const int tk = tid & 15;   // 0..15 -> key cols tk+16j (P) / dh cols tk*4.. (PV)
    const int bh = blockIdx.y;
    const int n0 = blockIdx.x * 64;
    const size_t qbase = ((size_t)bh * SEQ + n0) * DH;

    // load Q tile (64x64 r+i)
#pragma unroll
    for (int s = 0; s < 4; s++) {
        const int slot = tid + s * 256;
        const int row = slot >> 4;
        const int d4 = (slot & 15) << 2;
        *(float4*)(&Qr[row * AP + d4]) = *(const float4*)(&g_Qr[qbase + row * 64 + d4]);
        *(float4*)(&Qi[row * AP + d4]) = *(const float4*)(&g_Qi[qbase + row * 64 + d4]);
    }

    float accR[4][4] = {};
    float accI[4][4] = {};
    float rs[4] = {0.f, 0.f, 0.f, 0.f};

    for (int kt = 0; kt < 16; kt++) {
        __syncthreads();   // previous-iter P/V consumers done (also orders Q load on kt=0... actually load below)
        const size_t kbase = ((size_t)bh * SEQ + kt * 64) * DH;
#pragma unroll
        for (int s = 0; s < 4; s++) {
            const int slot = tid + s * 256;
            const int row = slot >> 4;
            const int d4 = (slot & 15) << 2;
            *(float4*)(&Kr[row * AP + d4]) = *(const float4*)(&g_Kr[kbase + row * 64 + d4]);
            *(float4*)(&Ki[row * AP + d4]) = *(const float4*)(&g_Ki[kbase + row * 64 + d4]);
            *(float4*)(&Vr[row * AP + d4]) = *(const float4*)(&g_Vr[kbase + row * 64 + d4]);
            *(float4*)(&Vi[row * AP + d4]) = *(const float4*)(&g_Vi[kbase + row * 64 + d4]);
        }
        __syncthreads();

        // ---- sim (4q x 4k per thread) ----
        float sr[4][4] = {};
        float si[4][4] = {};
#pragma unroll 8
        for (int d = 0; d < 64; d++) {
            float qr[4], qi[4], kr[4], ki[4];
#pragma unroll
            for (int i = 0; i < 4; i++) {
                qr[i] = Qr[(tq * 4 + i) * AP + d];
                qi[i] = Qi[(tq * 4 + i) * AP + d];
            }
#pragma unroll
            for (int j = 0; j < 4; j++) {
                const int k = tk + 16 * j;
                kr[j] = Kr[k * AP + d];
                ki[j] = Ki[k * AP + d];
            }
#pragma unroll
            for (int i = 0; i < 4; i++) {
#pragma unroll
                for (int j = 0; j < 4; j++) {
                    sr[i][j] = fmaf(qr[i],  kr[j], sr[i][j]);
                    sr[i][j] = fmaf(qi[i],  ki[j], sr[i][j]);
                    si[i][j] = fmaf(qi[i],  kr[j], si[i][j]);
                    si[i][j] = fmaf(-qr[i], ki[j], si[i][j]);
                }
            }
        }
        // ---- magnitude -> exp -> stage P ----
#pragma unroll
        for (int i = 0; i < 4; i++) {
            float rsum = 0.f;
#pragma unroll
            for (int j = 0; j < 4; j++) {
                const float mag = sqrtf(sr[i][j] * sr[i][j] + si[i][j] * si[i][j]) * 0.125f;
                const float p = __expf(mag);
                P[(tq * 4 + i) * AP + tk + 16 * j] = p;
                rsum += p;
            }
            rs[i] += rsum;
        }
        __syncthreads();

        // ---- O += P @ V (4q x 4d per thread) ----
#pragma unroll 4
        for (int k = 0; k < 64; k++) {
            float p[4];
#pragma unroll
            for (int i = 0; i < 4; i++) p[i] = P[(tq * 4 + i) * AP + k];
            const float4 vr4 = *(const float4*)(&Vr[k * AP + tk * 4]);
            const float4 vi4 = *(const float4*)(&Vi[k * AP + tk * 4]);
            const float vrv[4] = {vr4.x, vr4.y, vr4.z, vr4.w};
            const float viv[4] = {vi4.x, vi4.y, vi4.z, vi4.w};
#pragma unroll
            for (int i = 0; i < 4; i++) {
#pragma unroll
                for (int j = 0; j < 4; j++) {
                    accR[i][j] = fmaf(p[i], vrv[j], accR[i][j]);
                    accI[i][j] = fmaf(p[i], viv[j], accI[i][j]);
                }
            }
        }
    }
    __syncthreads();

    // ---- rowsum reduction across the 16 tk threads (reuse P as scratch) ----
#pragma unroll
    for (int i = 0; i < 4; i++) P[(tq * 4 + i) * AP + tk] = rs[i];
    __syncthreads();
    if (tid < 64) {
        float s = 0.f;
#pragma unroll
        for (int t = 0; t < 16; t++) s += P[tid * AP + t];
        rowsum[tid] = s;
    }
    __syncthreads();

    // ---- normalize + store to [B,N,DIM] layout ----
    const int b = bh >> 4, h = bh & 15;
#pragma unroll
    for (int i = 0; i < 4; i++) {
        const int q = tq * 4 + i;
        const float inv = 1.0f / rowsum[q];
        const size_t obase = ((size_t)b * SEQ + (n0 + q)) * DIMV + h * DH + tk * 4;
#pragma unroll
        for (int j = 0; j < 4; j++) {
            g_Or[obase + j] = accR[i][j] * inv;
            g_Oi[obase + j] = accI[i][j] * inv;
        }
    }
}

// =================== launcher ===================
extern "C" void kernel_launch(void* const* d_in, const int* in_sizes, int n_in,
                              void* d_out, int out_size)
{
    const float* xr = (const float*)d_in[0];
    const float* xi = (const float*)d_in[1];
    const float* Wr = (const float*)d_in[2];
    const float* Wi = (const float*)d_in[3];
    const float* br = (const float*)d_in[4];
    const float* bi = (const float*)d_in[5];

    float* outR = (float*)d_out;
    float* outI = outR + (size_t)BATCH * SEQ * DIMV;   // [2,B,N,D] imag plane

    const int ATTN_SMEM = (7 * 64 * AP + 64) * (int)sizeof(float);  // ~122 KB
    cudaFuncSetAttribute(attn_kernel, cudaFuncAttributeMaxDynamicSharedMemorySize,
                         ATTN_SMEM);

    const dim3 ggrid(16, 32);   // N/64 x M/128
    const size_t WSTRIDE = (size_t)DIMV * DIMV;

    // Q, K, V projections
    cgemm_kernel<<<ggrid, 256>>>(xr, xi, Wr + 0 * WSTRIDE, Wi + 0 * WSTRIDE,
                                 br + 0 * DIMV, bi + 0 * DIMV, nullptr, nullptr, 0);
    cgemm_kernel<<<ggrid, 256>>>(xr, xi, Wr + 1 * WSTRIDE, Wi + 1 * WSTRIDE,
                                 br + 1 * DIMV, bi + 1 * DIMV, nullptr, nullptr, 1);
    cgemm_kernel<<<ggrid, 256>>>(xr, xi, Wr + 2 * WSTRIDE, Wi + 2 * WSTRIDE,
                                 br + 2 * DIMV, bi + 2 * DIMV, nullptr, nullptr, 2);

    // attention
    attn_kernel<<<dim3(SEQ / 64, BH), 256, ATTN_SMEM>>>();

    // output projection -> d_out
    cgemm_kernel<<<ggrid, 256>>>(nullptr, nullptr, Wr + 3 * WSTRIDE, Wi + 3 * WSTRIDE,
                                 br + 3 * DIMV, bi + 3 * DIMV, outR, outI, 3);
}